// round 4
// baseline (speedup 1.0000x reference)
#include <cuda_runtime.h>
#include <cstdint>
#include <cstddef>
#include <float.h>

// Problem constants (static per reference setup_inputs)
#define BB 2
#define HH 32
#define SS 4096
#define DD 128
#define UU 16
#define TQ 3968          // S - RESID - S%GROUP
#define NG 31            // TQ / 128 groups along seq for K
#define PACKED_SEQ 992   // TQ / 4
#define RES_ROWS 257     // 2*RESID + 1

// Output layout (element offsets into float32 d_out, concatenated in reference return order)
static constexpr size_t OFF_QK    = 0;           // (B,H,992,128)   8,126,464
static constexpr size_t OFF_KSC   = 8126464;     // (B,H,31,128)      253,952
static constexpr size_t OFF_KMN   = 8380416;     // (B,H,31,128)      253,952
static constexpr size_t OFF_QV    = 8634368;     // (B,H,32,3968)   8,126,464
static constexpr size_t OFF_VSC   = 16760832;    // (B,H,1,3968)      253,952
static constexpr size_t OFF_VMN   = 17014784;    // (B,H,1,3968)      253,952
static constexpr size_t OFF_KRES  = 17268736;    // (B,H,257,128)   2,105,344
static constexpr size_t OFF_VRES  = 19374080;    // (B,H,257,128)   2,105,344
static constexpr size_t OFF_KFULL = 21479424;    // (B,H,4096,128) 33,554,432
static constexpr size_t OFF_VFULL = 55033856;    // (B,H,4096,128) 33,554,432
// total = 88,588,288

// Exact-match quantizer: jnp.round == round-half-even == rintf (RN mode);
// keep the IEEE division so codes match the reference bitwise.
__device__ __forceinline__ unsigned qcode(float x, float mn, float scale) {
    float t = rintf((x - mn) / scale);
    t = fminf(fmaxf(t, 0.0f), 15.0f);
    return (unsigned)t;
}

// ---------------- K quantization ----------------
// One block = one (b,h,seq-group g, d-half). 256 threads: dl = tid&63, sq = tid>>6.
// Stage 128(seq) x 64(d) fp32 tile in smem, per-d min/max over seq, pack 4 seq codes/u16.
__global__ void kquant_kernel(const float* __restrict__ k, float* __restrict__ out) {
    __shared__ float tile[128][65];      // pad -> conflict-free
    __shared__ float pmn[4][64], pmx[4][64];
    int tid = threadIdx.x;
    int dl  = tid & 63;
    int sq  = tid >> 6;                  // seq-quarter 0..3
    int blk = blockIdx.x;                // grid = 64 * 31 * 2
    int dh  = blk & 1;
    int g   = (blk >> 1) % NG;
    int bh  = blk / (2 * NG);
    int d   = dh * 64 + dl;

    const float* src = k + ((size_t)bh * SS + (size_t)g * 128) * DD + d;
    float mn = FLT_MAX, mx = -FLT_MAX;
    #pragma unroll 8
    for (int j = 0; j < 32; j++) {
        int s = sq * 32 + j;
        float val = src[(size_t)s * DD];
        tile[s][dl] = val;
        mn = fminf(mn, val);
        mx = fmaxf(mx, val);
    }
    pmn[sq][dl] = mn;
    pmx[sq][dl] = mx;
    __syncthreads();
    mn = fminf(fminf(pmn[0][dl], pmn[1][dl]), fminf(pmn[2][dl], pmn[3][dl]));
    mx = fmaxf(fmaxf(pmx[0][dl], pmx[1][dl]), fmaxf(pmx[2][dl], pmx[3][dl]));
    float scale = fmaxf((mx - mn) / 15.0f, 1e-6f);

    size_t qb = OFF_QK + ((size_t)bh * PACKED_SEQ + (size_t)g * 32) * DD + d;
    #pragma unroll
    for (int pi = 0; pi < 8; pi++) {
        int p = sq * 8 + pi;             // packed row within group (0..31)
        unsigned pk = 0;
        #pragma unroll
        for (int j = 0; j < 4; j++)
            pk |= qcode(tile[p * 4 + j][dl], mn, scale) << (j * 4);
        out[qb + (size_t)p * DD] = (float)pk;
    }
    if (sq == 0) {
        size_t sb = ((size_t)bh * NG + g) * DD + d;
        out[OFF_KSC + sb] = scale;
        out[OFF_KMN + sb] = mn;
    }
}

// ---------------- V quantization ----------------
// Group axis is contiguous D=128. One warp per token: float4 load + shfl min/max.
// Stage packed codes in smem [32][129] so the (B,H,32,Tq) store is coalesced.
__global__ void vquant_kernel(const float* __restrict__ v, float* __restrict__ out) {
    __shared__ unsigned pack_s[32][129];
    __shared__ float scale_s[128], min_s[128];
    int tid  = threadIdx.x;              // 256 threads = 8 warps
    int lane = tid & 31;
    int warp = tid >> 5;
    int bh   = blockIdx.x / NG;          // grid = 64 * 31
    int t0   = (blockIdx.x % NG) * 128;

    #pragma unroll 4
    for (int i = 0; i < 16; i++) {
        int tl = warp * 16 + i;          // local token 0..127
        int t  = t0 + tl;
        float4 x = ((const float4*)(v + ((size_t)bh * SS + t) * DD))[lane];
        float mn = fminf(fminf(x.x, x.y), fminf(x.z, x.w));
        float mx = fmaxf(fmaxf(x.x, x.y), fmaxf(x.z, x.w));
        #pragma unroll
        for (int o = 16; o > 0; o >>= 1) {
            mn = fminf(mn, __shfl_xor_sync(0xffffffffu, mn, o));
            mx = fmaxf(mx, __shfl_xor_sync(0xffffffffu, mx, o));
        }
        float scale = fmaxf((mx - mn) / 15.0f, 1e-6f);
        unsigned pk = qcode(x.x, mn, scale)
                    | (qcode(x.y, mn, scale) << 4)
                    | (qcode(x.z, mn, scale) << 8)
                    | (qcode(x.w, mn, scale) << 12);
        pack_s[lane][tl] = pk;
        if (lane == 0) { scale_s[tl] = scale; min_s[tl] = mn; }
    }
    __syncthreads();

    size_t qb = OFF_QV + (size_t)bh * 32 * TQ + t0;
    #pragma unroll
    for (int i = tid; i < 32 * 128; i += 256) {
        int l = i >> 7, tl = i & 127;
        out[qb + (size_t)l * TQ + tl] = (float)pack_s[l][tl];
    }
    if (tid < 128) {
        size_t sb = (size_t)bh * TQ + t0 + tid;
        out[OFF_VSC + sb] = scale_s[tid];
        out[OFF_VMN + sb] = min_s[tid];
    }
}

// ---------------- Residual buffers (float4) ----------------
// k_resid/v_resid: (B,H,257,128); rows [0,128) = k/v[:, :, TQ:TQ+128], rest zero.
// 257*128 floats per (b,h) image = 8224 float4s; row = 32 float4s.
__global__ void resid_kernel(const float* __restrict__ k, const float* __restrict__ v,
                             float* __restrict__ out) {
    int idx = blockIdx.x * 256 + threadIdx.x;   // 526,336 threads (= 2,105,344/4)
    int d4   = idx & 31;                         // float4 within row
    int rest = idx >> 5;
    int s2   = rest % RES_ROWS;
    int bh   = rest / RES_ROWS;
    float4 kv = make_float4(0.f, 0.f, 0.f, 0.f);
    float4 vv = kv;
    if (s2 < 128) {
        size_t si = (((size_t)bh * SS + TQ + s2) * DD) / 4 + d4;
        kv = ((const float4*)k)[si];
        vv = ((const float4*)v)[si];
    }
    ((float4*)(out + OFF_KRES))[idx] = kv;
    ((float4*)(out + OFF_VRES))[idx] = vv;
}

// ---------------- Scatter new tokens into (zeroed) full caches (float4) ----------------
__global__ void scatter_kernel(const float* __restrict__ kn, const float* __restrict__ vn,
                               const int* __restrict__ cs, const int* __restrict__ qcs,
                               float* __restrict__ out) {
    int idx = blockIdx.x * 256 + threadIdx.x;   // 32,768 threads (= 131,072/4)
    int d4 = idx & 31;
    int u  = (idx >> 5) & 15;
    int h  = (idx >> 9) & 31;
    int b  = idx >> 14;
    int off = cs[b] - qcs[b];
    size_t dst = ((((size_t)(b * HH + h)) * SS + (size_t)(off + u)) * DD) / 4 + d4;
    ((float4*)(out + OFF_KFULL))[dst] = ((const float4*)kn)[idx];
    ((float4*)(out + OFF_VFULL))[dst] = ((const float4*)vn)[idx];
}

extern "C" void kernel_launch(void* const* d_in, const int* in_sizes, int n_in,
                              void* d_out, int out_size) {
    const float* k   = (const float*)d_in[0];
    const float* v   = (const float*)d_in[1];
    const float* kn  = (const float*)d_in[2];
    const float* vn  = (const float*)d_in[3];
    const int*   cs  = (const int*)d_in[4];
    const int*   qcs = (const int*)d_in[5];
    float* out = (float*)d_out;

    // k_full + v_full are contiguous: one big zero-fill (memset node, full write BW),
    // then the tiny per-batch scatter of k_new/v_new on top.
    cudaMemsetAsync(out + OFF_KFULL, 0, (size_t)2 * 33554432 * sizeof(float), 0);
    scatter_kernel<<<128, 256>>>(kn, vn, cs, qcs, out);

    kquant_kernel<<<64 * NG * 2, 256>>>(k, out);
    vquant_kernel<<<64 * NG, 256>>>(v, out);
    resid_kernel<<<2056, 256>>>(k, v, out);
}

// round 7
// speedup vs baseline: 1.0885x; 1.0885x over previous
#include <cuda_runtime.h>
#include <cstdint>
#include <cstddef>
#include <float.h>

// Problem constants (static per reference setup_inputs)
#define BB 2
#define HH 32
#define SS 4096
#define DD 128
#define UU 16
#define TQ 3968          // S - RESID - S%GROUP
#define NG 31            // TQ / 128 groups along seq for K
#define PACKED_SEQ 992   // TQ / 4
#define RES_ROWS 257     // 2*RESID + 1

// Output layout (element offsets into float32 d_out, concatenated in reference return order)
static constexpr size_t OFF_QK    = 0;           // (B,H,992,128)   8,126,464
static constexpr size_t OFF_KSC   = 8126464;     // (B,H,31,128)      253,952
static constexpr size_t OFF_KMN   = 8380416;     // (B,H,31,128)      253,952
static constexpr size_t OFF_QV    = 8634368;     // (B,H,32,3968)   8,126,464
static constexpr size_t OFF_VSC   = 16760832;    // (B,H,1,3968)      253,952
static constexpr size_t OFF_VMN   = 17014784;    // (B,H,1,3968)      253,952
static constexpr size_t OFF_KRES  = 17268736;    // (B,H,257,128)   2,105,344
static constexpr size_t OFF_VRES  = 19374080;    // (B,H,257,128)   2,105,344
static constexpr size_t OFF_KFULL = 21479424;    // (B,H,4096,128) 33,554,432
static constexpr size_t OFF_VFULL = 55033856;    // (B,H,4096,128) 33,554,432
// total = 88,588,288

// Section block counts (256 threads/block everywhere)
#define NKQ  3968        // kquant: 64 bh * 31 groups * 2 d-halves
#define NVQ  1984        // vquant: 64 bh * 31 token-chunks
#define NRES 2056        // resid:  2,105,344 floats / 4 / 256
#define NFILL 8192       // fill:   33,554,432/4 float4 per array / 1024 per block
#define B_VQ   (NKQ)
#define B_RES  (NKQ + NVQ)
#define B_FILL (NKQ + NVQ + NRES)
#define NBLOCKS (NKQ + NVQ + NRES + NFILL)   // 16200

// Quantizer: jnp.round == round-half-even == rintf (RN mode); IEEE division.
__device__ __forceinline__ unsigned qcode(float x, float mn, float scale) {
    float t = rintf((x - mn) / scale);
    t = fminf(fmaxf(t, 0.0f), 15.0f);
    return (unsigned)t;
}

__global__ void __launch_bounds__(256) fused_kvcache_kernel(
    const float* __restrict__ k,  const float* __restrict__ v,
    const float* __restrict__ kn, const float* __restrict__ vn,
    const int* __restrict__ cs,   const int* __restrict__ qcs,
    float* __restrict__ out)
{
    __shared__ union {
        struct { float tile[128][65]; float pmn[4][64]; float pmx[4][64]; } kq;  // 35328 B
        struct { unsigned pack[32][129]; float scale[128]; float mnv[128]; } vq; // 17536 B
    } sm;

    int blk = blockIdx.x;
    int tid = threadIdx.x;

    if (blk < B_VQ) {
        // ---------------- K quantization ----------------
        // One block = (b,h,seq-group g, d-half). dl = tid&63, sq = tid>>6.
        int dl  = tid & 63;
        int sq  = tid >> 6;
        int dh  = blk & 1;
        int g   = (blk >> 1) % NG;
        int bh  = blk / (2 * NG);
        int d   = dh * 64 + dl;

        const float* src = k + ((size_t)bh * SS + (size_t)g * 128) * DD + d;
        float mn = FLT_MAX, mx = -FLT_MAX;
        #pragma unroll 8
        for (int j = 0; j < 32; j++) {
            int s = sq * 32 + j;
            float val = src[(size_t)s * DD];
            sm.kq.tile[s][dl] = val;
            mn = fminf(mn, val);
            mx = fmaxf(mx, val);
        }
        sm.kq.pmn[sq][dl] = mn;
        sm.kq.pmx[sq][dl] = mx;
        __syncthreads();
        mn = fminf(fminf(sm.kq.pmn[0][dl], sm.kq.pmn[1][dl]),
                   fminf(sm.kq.pmn[2][dl], sm.kq.pmn[3][dl]));
        mx = fmaxf(fmaxf(sm.kq.pmx[0][dl], sm.kq.pmx[1][dl]),
                   fmaxf(sm.kq.pmx[2][dl], sm.kq.pmx[3][dl]));
        float scale = fmaxf((mx - mn) / 15.0f, 1e-6f);

        size_t qb = OFF_QK + ((size_t)bh * PACKED_SEQ + (size_t)g * 32) * DD + d;
        #pragma unroll
        for (int pi = 0; pi < 8; pi++) {
            int p = sq * 8 + pi;
            unsigned pk = 0;
            #pragma unroll
            for (int j = 0; j < 4; j++)
                pk |= qcode(sm.kq.tile[p * 4 + j][dl], mn, scale) << (j * 4);
            out[qb + (size_t)p * DD] = (float)pk;
        }
        if (sq == 0) {
            size_t sb = ((size_t)bh * NG + g) * DD + d;
            out[OFF_KSC + sb] = scale;
            out[OFF_KMN + sb] = mn;
        }
    } else if (blk < B_RES) {
        // ---------------- V quantization ----------------
        // Warp per token: float4 load + shfl butterfly min/max over contiguous D=128.
        int lb   = blk - B_VQ;
        int lane = tid & 31;
        int warp = tid >> 5;
        int bh   = lb / NG;
        int t0   = (lb % NG) * 128;

        #pragma unroll 4
        for (int i = 0; i < 16; i++) {
            int tl = warp * 16 + i;
            int t  = t0 + tl;
            float4 x = ((const float4*)(v + ((size_t)bh * SS + t) * DD))[lane];
            float mn = fminf(fminf(x.x, x.y), fminf(x.z, x.w));
            float mx = fmaxf(fmaxf(x.x, x.y), fmaxf(x.z, x.w));
            #pragma unroll
            for (int o = 16; o > 0; o >>= 1) {
                mn = fminf(mn, __shfl_xor_sync(0xffffffffu, mn, o));
                mx = fmaxf(mx, __shfl_xor_sync(0xffffffffu, mx, o));
            }
            float scale = fmaxf((mx - mn) / 15.0f, 1e-6f);
            unsigned pk = qcode(x.x, mn, scale)
                        | (qcode(x.y, mn, scale) << 4)
                        | (qcode(x.z, mn, scale) << 8)
                        | (qcode(x.w, mn, scale) << 12);
            sm.vq.pack[lane][tl] = pk;
            if (lane == 0) { sm.vq.scale[tl] = scale; sm.vq.mnv[tl] = mn; }
        }
        __syncthreads();

        size_t qb = OFF_QV + (size_t)bh * 32 * TQ + t0;
        #pragma unroll
        for (int i = tid; i < 32 * 128; i += 256) {
            int l = i >> 7, tl = i & 127;
            out[qb + (size_t)l * TQ + tl] = (float)sm.vq.pack[l][tl];
        }
        if (tid < 128) {
            size_t sb = (size_t)bh * TQ + t0 + tid;
            out[OFF_VSC + sb] = sm.vq.scale[tid];
            out[OFF_VMN + sb] = sm.vq.mnv[tid];
        }
    } else if (blk < B_FILL) {
        // ---------------- Residual buffers (float4) ----------------
        int idx  = (blk - B_RES) * 256 + tid;     // 526,336 float4s
        int d4   = idx & 31;
        int rest = idx >> 5;
        int s2   = rest % RES_ROWS;
        int bh   = rest / RES_ROWS;
        float4 kv = make_float4(0.f, 0.f, 0.f, 0.f);
        float4 vv = kv;
        if (s2 < 128) {
            size_t si = (((size_t)bh * SS + TQ + s2) * DD) / 4 + d4;
            kv = ((const float4*)k)[si];
            vv = ((const float4*)v)[si];
        }
        ((float4*)(out + OFF_KRES))[idx] = kv;
        ((float4*)(out + OFF_VRES))[idx] = vv;
    } else {
        // ---------------- k_full/v_full fill + scatter (float4) ----------------
        // Each thread writes 4 float4s to each array; value is k_new/v_new if the
        // row hits the per-batch scatter window, else zero.
        int fb = blk - B_FILL;
        const float4* kn4 = (const float4*)kn;
        const float4* vn4 = (const float4*)vn;
        float4* ok4 = (float4*)(out + OFF_KFULL);
        float4* ov4 = (float4*)(out + OFF_VFULL);
        #pragma unroll
        for (int j = 0; j < 4; j++) {
            int idx = fb * 1024 + j * 256 + tid;  // float4 index in (B,H,S,D/4)
            int d4 = idx & 31;
            int s  = (idx >> 5) & (SS - 1);
            int bh = idx >> 17;
            int b  = bh >> 5;
            int u  = s - (__ldg(cs + b) - __ldg(qcs + b));
            float4 kv = make_float4(0.f, 0.f, 0.f, 0.f);
            float4 vv = kv;
            if ((unsigned)u < UU) {
                int sidx = ((bh * UU + u) << 5) + d4;
                kv = kn4[sidx];
                vv = vn4[sidx];
            }
            ok4[idx] = kv;
            ov4[idx] = vv;
        }
    }
}

extern "C" void kernel_launch(void* const* d_in, const int* in_sizes, int n_in,
                              void* d_out, int out_size) {
    const float* k   = (const float*)d_in[0];
    const float* v   = (const float*)d_in[1];
    const float* kn  = (const float*)d_in[2];
    const float* vn  = (const float*)d_in[3];
    const int*   cs  = (const int*)d_in[4];
    const int*   qcs = (const int*)d_in[5];
    float* out = (float*)d_out;

    fused_kvcache_kernel<<<NBLOCKS, 256>>>(k, v, kn, vn, cs, qcs, out);
}